// round 15
// baseline (speedup 1.0000x reference)
#include <cuda_runtime.h>

#define BATCH 256
#define SEQ   2048
#define EMBD  16
#define HIDD  32
#define GATE  128
#define VOCAB 5000

typedef unsigned long long u64;
typedef unsigned int       u32;

// Vocab-indexed input projection table: vp[v][j] = (i,f,g,o) pre-activations
// for token v, hid j. 2.56 MB -> L2-resident.
__device__ float4 g_vp[(size_t)VOCAB * HIDD];

__device__ __forceinline__ u64 pack2(float lo, float hi){
    u64 r; asm("mov.b64 %0, {%1,%2};" : "=l"(r) : "f"(lo), "f"(hi)); return r;
}
__device__ __forceinline__ void unpack2(u64 v, float& lo, float& hi){
    asm("mov.b64 {%0,%1}, %2;" : "=f"(lo), "=f"(hi) : "l"(v));
}
__device__ __forceinline__ u64 ffma2(u64 a, u64 b, u64 c){
    u64 d; asm("fma.rn.f32x2 %0, %1, %2, %3;" : "=l"(d) : "l"(a), "l"(b), "l"(c)); return d;
}
__device__ __forceinline__ u64 fadd2(u64 a, u64 b){
    u64 d; asm("add.rn.f32x2 %0, %1, %2;" : "=l"(d) : "l"(a), "l"(b)); return d;
}
__device__ __forceinline__ float tanha(float x){
    float y; asm("tanh.approx.f32 %0, %1;" : "=f"(y) : "f"(x)); return y;
}
// sigmoid(z) = 0.5 + 0.5*tanh(z/2)
__device__ __forceinline__ float sigt(float z){
    return fmaf(0.5f, tanha(0.5f * z), 0.5f);
}
__device__ __forceinline__ u32 smem_u32(const void* p){
    u32 a;
    asm("{ .reg .u64 t; cvta.to.shared.u64 t, %1; cvt.u32.u64 %0, t; }"
        : "=r"(a) : "l"(p));
    return a;
}
__device__ __forceinline__ void sts64f(u32 addr, float a, float b){
    asm volatile("st.shared.v2.f32 [%0], {%1,%2};" :: "r"(addr), "f"(a), "f"(b) : "memory");
}
// one LDS.128 -> two {h,h} u64 operands (duplicated-pair layout, no packing)
#define LDSV2(qa, qb, addr)                                             \
    asm volatile("ld.shared.v2.u64 {%0,%1}, [%2];"                      \
        : "=l"(qa), "=l"(qb) : "r"(addr));

// ─────────────── Phase 0: vp[v] = emb[v]@Wk + b  (5000 rows, ~5us) ──────────
__global__ __launch_bounds__(128) void vproj_kernel(
    const float* __restrict__ emb,
    const float* __restrict__ Wk,
    const float* __restrict__ bias)
{
    const int j   = threadIdx.x & 31;
    const int wid = (blockIdx.x << 2) + (threadIdx.x >> 5);
    const int nw  = gridDim.x << 2;

    float wk0[EMBD], wk1[EMBD], wk2[EMBD], wk3[EMBD];
    #pragma unroll
    for (int e = 0; e < EMBD; e++){
        wk0[e] = Wk[e*GATE + j];
        wk1[e] = Wk[e*GATE + j + 32];
        wk2[e] = Wk[e*GATE + j + 64];
        wk3[e] = Wk[e*GATE + j + 96];
    }
    const float b0 = bias[j], b1 = bias[j+32], b2 = bias[j+64], b3 = bias[j+96];

    for (int v = wid; v < VOCAB; v += nw){
        const float* x = emb + v * EMBD;
        float zi = b0, zf = b1, zg = b2, zo = b3;
        #pragma unroll
        for (int e = 0; e < EMBD; e++){
            const float xe = x[e];
            zi = fmaf(xe, wk0[e], zi);
            zf = fmaf(xe, wk1[e], zf);
            zg = fmaf(xe, wk2[e], zg);
            zo = fmaf(xe, wk3[e], zo);
        }
        g_vp[(size_t)v * HIDD + j] = make_float4(zi, zf, zg, zo);
    }
}

// ─────────────── Phase 2: R14 structure + f32x2 dual-FMA matvec ─────────────
// One warp per sequence; lane j owns hid j + packed gate pairs (i,f)/(g,o).
// h stored DUPLICATED in smem ({h,h} per hid) so ld.shared.v2.u64 delivers
// ready {h_k,h_k} f32x2 operands. 64 FFMA2/step (128-slot floor if FFMA2 is
// dual-rate like HFMA2). Spill-proof named rings, vp gather, barrier-free
// volatile STS->LDS handoff — all carried over from the R14 record holder.
#define MACA(k)  aI0 = ffma2(q##k, wIF[k], aI0);  aG0 = ffma2(q##k, wGO[k], aG0);
#define MACB(k)  aI1 = ffma2(q##k, wIF[k], aI1);  aG1 = ffma2(q##k, wGO[k], aG1);

#define LSTM_BODY(Z, TKC, TKZ, tt)                                      \
{                                                                       \
    const float4 z4  = Z;                                               \
    const int    tok = TKC;                                             \
    TKC = tptr[min((tt) + 4, SEQ - 1)];   /* token for step tt+4 */     \
    Z   = vpj[(size_t)(TKZ) * HIDD];      /* zx for step tt+2 */        \
    u64 q0,q1,q2,q3,q4,q5,q6,q7,q8,q9,q10,q11,q12,q13,q14,q15;          \
    u64 q16,q17,q18,q19,q20,q21,q22,q23,q24,q25,q26,q27,q28,q29,q30,q31;\
    LDSV2(q0,  q1,  hbase +   0u)  LDSV2(q2,  q3,  hbase +  16u)        \
    LDSV2(q4,  q5,  hbase +  32u)  LDSV2(q6,  q7,  hbase +  48u)        \
    LDSV2(q8,  q9,  hbase +  64u)  LDSV2(q10, q11, hbase +  80u)        \
    LDSV2(q12, q13, hbase +  96u)  LDSV2(q14, q15, hbase + 112u)        \
    LDSV2(q16, q17, hbase + 128u)  LDSV2(q18, q19, hbase + 144u)        \
    LDSV2(q20, q21, hbase + 160u)  LDSV2(q22, q23, hbase + 176u)        \
    LDSV2(q24, q25, hbase + 192u)  LDSV2(q26, q27, hbase + 208u)        \
    LDSV2(q28, q29, hbase + 224u)  LDSV2(q30, q31, hbase + 240u)        \
    u64 aI0 = pack2(z4.x, z4.y);                                        \
    u64 aG0 = pack2(z4.z, z4.w);                                        \
    u64 aI1 = 0, aG1 = 0;                                               \
    MACA(0)  MACB(16)  MACA(1)  MACB(17)                                \
    MACA(2)  MACB(18)  MACA(3)  MACB(19)                                \
    MACA(4)  MACB(20)  MACA(5)  MACB(21)                                \
    MACA(6)  MACB(22)  MACA(7)  MACB(23)                                \
    MACA(8)  MACB(24)  MACA(9)  MACB(25)                                \
    MACA(10) MACB(26)  MACA(11) MACB(27)                                \
    MACA(12) MACB(28)  MACA(13) MACB(29)                                \
    MACA(14) MACB(30)  MACA(15) MACB(31)                                \
    const u64 zifs = fadd2(aI0, aI1);                                   \
    const u64 zgos = fadd2(aG0, aG1);                                   \
    float zi, zf, zg, zo;                                               \
    unpack2(zifs, zi, zf);                                              \
    unpack2(zgos, zg, zo);                                              \
    const float gi = sigt(zi);                                          \
    const float gf = sigt(zf);                                          \
    const float gg = tanha(zg);                                         \
    const float go = sigt(zo);                                          \
    const float cn = fmaf(gf, c, gi * gg);                              \
    const float hn = go * tanha(cn);                                    \
    const bool  m  = (tok != 0);                                        \
    c = m ? cn : c;                                                     \
    h = m ? hn : h;                                                     \
    sts64f(haddr, h, h);                                                \
    optr[(size_t)(tt) * HIDD] = h;                                      \
}

__global__ __launch_bounds__(128) void rec_kernel(
    const int*   __restrict__ tokens,
    const float* __restrict__ Wr,
    float*       __restrict__ out)
{
    __shared__ float hs[4][2 * HIDD];     // duplicated {h,h} pairs per warp

    const int w = threadIdx.x >> 5;
    const int j = threadIdx.x & 31;
    const int b = blockIdx.x * 4 + w;

    // packed weights: wIF[k] = {Wr[k][j], Wr[k][j+32]}, wGO likewise
    u64 wIF[HIDD], wGO[HIDD];             // constant indices only
    #pragma unroll
    for (int k = 0; k < HIDD; k++){
        wIF[k] = pack2(Wr[k*GATE + j],      Wr[k*GATE + j + 32]);
        wGO[k] = pack2(Wr[k*GATE + j + 64], Wr[k*GATE + j + 96]);
    }

    const u32 hbase = smem_u32(hs[w]);
    const u32 haddr = hbase + (u32)j * 8u;

    const float4* __restrict__ vpj  = g_vp + j;
    const int*    __restrict__ tptr = tokens + b * SEQ;
    float* optr = out + (size_t)b * SEQ * HIDD + j;

    // token ring distance 4; z ring distance 2 (slot = t parity)
    int tA = tptr[0], tB = tptr[1], tC = tptr[2], tD = tptr[3];
    float4 zA = vpj[(size_t)tA * HIDD];
    float4 zB = vpj[(size_t)tB * HIDD];

    sts64f(haddr, 0.0f, 0.0f);
    float h = 0.0f, c = 0.0f;

    for (int t = 0; t < SEQ; t += 4){
        LSTM_BODY(zA, tA, tC, t + 0)
        LSTM_BODY(zB, tB, tD, t + 1)
        LSTM_BODY(zA, tC, tA, t + 2)
        LSTM_BODY(zB, tD, tB, t + 3)
    }
}

extern "C" void kernel_launch(void* const* d_in, const int* in_sizes, int n_in,
                              void* d_out, int out_size)
{
    (void)in_sizes; (void)n_in; (void)out_size;
    const int*   tokens = (const int*)  d_in[0];
    const float* emb    = (const float*)d_in[1];
    const float* Wk     = (const float*)d_in[2];
    const float* Wr     = (const float*)d_in[3];
    const float* bias   = (const float*)d_in[4];
    float* out = (float*)d_out;

    vproj_kernel<<<40, 128>>>(emb, Wk, bias);
    rec_kernel<<<BATCH / 4, 128>>>(tokens, Wr, out);
}

// round 16
// speedup vs baseline: 1.7154x; 1.7154x over previous
#include <cuda_runtime.h>
#include <cuda_fp16.h>

#define BATCH 256
#define SEQ   2048
#define EMBD  16
#define HIDD  32
#define GATE  128
#define VOCAB 5000

typedef unsigned int u32;

// Vocab-indexed input projection table (fp32): vp[v][j] = (i,f,g,o). 2.56MB, L2.
__device__ float4 g_vp[(size_t)VOCAB * HIDD];

__device__ __forceinline__ float tanha(float x){
    float y; asm("tanh.approx.f32 %0, %1;" : "=f"(y) : "f"(x)); return y;
}
// sigmoid(z) = 0.5 + 0.5*tanh(z/2)
__device__ __forceinline__ float sigt(float z){
    return fmaf(0.5f, tanha(0.5f * z), 0.5f);
}
__device__ __forceinline__ u32 smem_u32(const void* p){
    u32 a;
    asm("{ .reg .u64 t; cvta.to.shared.u64 t, %1; cvt.u32.u64 %0, t; }"
        : "=r"(a) : "l"(p));
    return a;
}
__device__ __forceinline__ void sts32u(u32 addr, u32 v){
    asm volatile("st.shared.u32 [%0], %1;" :: "r"(addr), "r"(v) : "memory");
}
__device__ __forceinline__ uint4 lds128u(u32 addr){
    uint4 v;
    asm volatile("ld.shared.v4.u32 {%0,%1,%2,%3}, [%4];"
        : "=r"(v.x), "=r"(v.y), "=r"(v.z), "=r"(v.w) : "r"(addr));
    return v;
}
__device__ __forceinline__ __half2 u32h2(u32 v){
    __half2 r; asm("mov.b32 %0, %1;" : "=r"(*(u32*)&r) : "r"(v)); return r;
}
__device__ __forceinline__ u32 h2u32(__half2 v){
    u32 r; asm("mov.b32 %0, %1;" : "=r"(r) : "r"(*(u32*)&v)); return r;
}

// ─────────────── Phase 0: vp[v] = emb[v]@Wk + b  (fp32, ~5us) ───────────────
__global__ __launch_bounds__(128) void vproj_kernel(
    const float* __restrict__ emb,
    const float* __restrict__ Wk,
    const float* __restrict__ bias)
{
    const int j   = threadIdx.x & 31;
    const int wid = (blockIdx.x << 2) + (threadIdx.x >> 5);
    const int nw  = gridDim.x << 2;

    float wk0[EMBD], wk1[EMBD], wk2[EMBD], wk3[EMBD];
    #pragma unroll
    for (int e = 0; e < EMBD; e++){
        wk0[e] = Wk[e*GATE + j];
        wk1[e] = Wk[e*GATE + j + 32];
        wk2[e] = Wk[e*GATE + j + 64];
        wk3[e] = Wk[e*GATE + j + 96];
    }
    const float b0 = bias[j], b1 = bias[j+32], b2 = bias[j+64], b3 = bias[j+96];

    for (int v = wid; v < VOCAB; v += nw){
        const float* x = emb + v * EMBD;
        float zi = b0, zf = b1, zg = b2, zo = b3;
        #pragma unroll
        for (int e = 0; e < EMBD; e++){
            const float xe = x[e];
            zi = fmaf(xe, wk0[e], zi);
            zf = fmaf(xe, wk1[e], zf);
            zg = fmaf(xe, wk2[e], zg);
            zo = fmaf(xe, wk3[e], zo);
        }
        g_vp[(size_t)v * HIDD + j] = make_float4(zi, zf, zg, zo);
    }
}

// ─────────────── Phase 2: R14 structure + HFMA2 dual-rate matvec ────────────
// One warp/sequence; lane j owns hid j + gate cols. The Wr matvec runs in
// fp16x2 (HFMA2 = 2 MACs per rt2 slot -> 128-cycle pipe floor, half of R14's
// scalar FFMA). h is duplicated {h,h} half2 in smem (one cvt+pack per step;
// LDS.128 yields 4 ready operands). 8 split 8-deep fp16 chains + fp16 pair
// tree; final reduce, zx add, gates, c, h ALL fp32 (long-horizon c-path keeps
// full precision). Everything else identical to the R14 record holder.
#define MAC8(aif, ago, R, base)                                   \
    aif = __hfma2(u32h2((R).x), wIF[(base)  ], aif);              \
    ago = __hfma2(u32h2((R).x), wGO[(base)  ], ago);              \
    aif = __hfma2(u32h2((R).y), wIF[(base)+1], aif);              \
    ago = __hfma2(u32h2((R).y), wGO[(base)+1], ago);              \
    aif = __hfma2(u32h2((R).z), wIF[(base)+2], aif);              \
    ago = __hfma2(u32h2((R).z), wGO[(base)+2], ago);              \
    aif = __hfma2(u32h2((R).w), wIF[(base)+3], aif);              \
    ago = __hfma2(u32h2((R).w), wGO[(base)+3], ago);

#define LSTM_BODY(Z, TKC, TKZ, tt)                                      \
{                                                                       \
    const float4 z4  = Z;                                               \
    const int    tok = TKC;                                             \
    TKC = tptr[min((tt) + 4, SEQ - 1)];   /* token for step tt+4 */     \
    Z   = vpj[(size_t)(TKZ) * HIDD];      /* zx for step tt+2  */       \
    const uint4 r0 = lds128u(hbase +   0u);                             \
    const uint4 r1 = lds128u(hbase +  16u);                             \
    const uint4 r2 = lds128u(hbase +  32u);                             \
    const uint4 r3 = lds128u(hbase +  48u);                             \
    const uint4 r4 = lds128u(hbase +  64u);                             \
    const uint4 r5 = lds128u(hbase +  80u);                             \
    const uint4 r6 = lds128u(hbase +  96u);                             \
    const uint4 r7 = lds128u(hbase + 112u);                             \
    __half2 aIF0 = zeroh, aIF1 = zeroh, aIF2 = zeroh, aIF3 = zeroh;     \
    __half2 aGO0 = zeroh, aGO1 = zeroh, aGO2 = zeroh, aGO3 = zeroh;     \
    MAC8(aIF0, aGO0, r0,  0)   MAC8(aIF0, aGO0, r1,  4)                 \
    MAC8(aIF1, aGO1, r2,  8)   MAC8(aIF1, aGO1, r3, 12)                 \
    MAC8(aIF2, aGO2, r4, 16)   MAC8(aIF2, aGO2, r5, 20)                 \
    MAC8(aIF3, aGO3, r6, 24)   MAC8(aIF3, aGO3, r7, 28)                 \
    const __half2 sIF = __hadd2(__hadd2(aIF0, aIF1), __hadd2(aIF2, aIF3)); \
    const __half2 sGO = __hadd2(__hadd2(aGO0, aGO1), __hadd2(aGO2, aGO3)); \
    const float2 fIF = __half22float2(sIF);                             \
    const float2 fGO = __half22float2(sGO);                             \
    const float gi = sigt(z4.x + fIF.x);                                \
    const float gf = sigt(z4.y + fIF.y);                                \
    const float gg = tanha(z4.z + fGO.x);                               \
    const float go = sigt(z4.w + fGO.y);                                \
    const float cn = fmaf(gf, c, gi * gg);                              \
    const float hn = go * tanha(cn);                                    \
    const bool  m  = (tok != 0);                                        \
    c = m ? cn : c;                                                     \
    h = m ? hn : h;                                                     \
    sts32u(haddr, h2u32(__float2half2_rn(h)));                          \
    optr[(size_t)(tt) * HIDD] = h;                                      \
}

__global__ __launch_bounds__(128) void rec_kernel(
    const int*   __restrict__ tokens,
    const float* __restrict__ Wr,
    float*       __restrict__ out)
{
    __shared__ u32 hs[4][HIDD];           // {h,h} half2 per hid, per warp

    const int w = threadIdx.x >> 5;
    const int j = threadIdx.x & 31;
    const int b = blockIdx.x * 4 + w;

    // fp16x2 packed weights: wIF[k] = {wi[k], wf[k]}, wGO[k] = {wg[k], wo[k]}
    __half2 wIF[HIDD], wGO[HIDD];         // constant indices only
    #pragma unroll
    for (int k = 0; k < HIDD; k++){
        wIF[k] = __floats2half2_rn(Wr[k*GATE + j],      Wr[k*GATE + j + 32]);
        wGO[k] = __floats2half2_rn(Wr[k*GATE + j + 64], Wr[k*GATE + j + 96]);
    }
    const __half2 zeroh = __float2half2_rn(0.0f);

    const u32 hbase = smem_u32(hs[w]);
    const u32 haddr = hbase + (u32)j * 4u;

    const float4* __restrict__ vpj  = g_vp + j;
    const int*    __restrict__ tptr = tokens + b * SEQ;
    float* optr = out + (size_t)b * SEQ * HIDD + j;

    // token ring distance 4; z ring distance 2 (slot = t parity)
    int tA = tptr[0], tB = tptr[1], tC = tptr[2], tD = tptr[3];
    float4 zA = vpj[(size_t)tA * HIDD];
    float4 zB = vpj[(size_t)tB * HIDD];

    sts32u(haddr, 0u);
    float h = 0.0f, c = 0.0f;

    for (int t = 0; t < SEQ; t += 4){
        LSTM_BODY(zA, tA, tC, t + 0)
        LSTM_BODY(zB, tB, tD, t + 1)
        LSTM_BODY(zA, tC, tA, t + 2)
        LSTM_BODY(zB, tD, tB, t + 3)
    }
}

extern "C" void kernel_launch(void* const* d_in, const int* in_sizes, int n_in,
                              void* d_out, int out_size)
{
    (void)in_sizes; (void)n_in; (void)out_size;
    const int*   tokens = (const int*)  d_in[0];
    const float* emb    = (const float*)d_in[1];
    const float* Wk     = (const float*)d_in[2];
    const float* Wr     = (const float*)d_in[3];
    const float* bias   = (const float*)d_in[4];
    float* out = (float*)d_out;

    vproj_kernel<<<40, 128>>>(emb, Wk, bias);
    rec_kernel<<<BATCH / 4, 128>>>(tokens, Wr, out);
}

// round 17
// speedup vs baseline: 1.9052x; 1.1106x over previous
#include <cuda_runtime.h>
#include <cuda_fp16.h>

#define BATCH 256
#define SEQ   2048
#define EMBD  16
#define HIDD  32
#define GATE  128
#define VOCAB 5000

typedef unsigned int u32;

// Vocab-indexed input projection table (fp32): vp[v][j] = (i,f,g,o). 2.56MB, L2.
__device__ float4 g_vp[(size_t)VOCAB * HIDD];

__device__ __forceinline__ float tanha(float x){
    float y; asm("tanh.approx.f32 %0, %1;" : "=f"(y) : "f"(x)); return y;
}
// sigmoid(z) = 0.5 + 0.5*tanh(z/2)
__device__ __forceinline__ float sigt(float z){
    return fmaf(0.5f, tanha(0.5f * z), 0.5f);
}
__device__ __forceinline__ u32 smem_u32(const void* p){
    u32 a;
    asm("{ .reg .u64 t; cvta.to.shared.u64 t, %1; cvt.u32.u64 %0, t; }"
        : "=r"(a) : "l"(p));
    return a;
}
__device__ __forceinline__ void sts32u(u32 addr, u32 v){
    asm volatile("st.shared.u32 [%0], %1;" :: "r"(addr), "r"(v) : "memory");
}
__device__ __forceinline__ uint4 lds128u(u32 addr){
    uint4 v;
    asm volatile("ld.shared.v4.u32 {%0,%1,%2,%3}, [%4];"
        : "=r"(v.x), "=r"(v.y), "=r"(v.z), "=r"(v.w) : "r"(addr));
    return v;
}
__device__ __forceinline__ __half2 u32h2(u32 v){
    __half2 r; asm("mov.b32 %0, %1;" : "=r"(*(u32*)&r) : "r"(v)); return r;
}
__device__ __forceinline__ u32 h2u32(__half2 v){
    u32 r; asm("mov.b32 %0, %1;" : "=r"(r) : "r"(*(u32*)&v)); return r;
}

// ─────────────── Phase 0: vp[v] = emb[v]@Wk + b  (fp32, ~5us) ───────────────
__global__ __launch_bounds__(128) void vproj_kernel(
    const float* __restrict__ emb,
    const float* __restrict__ Wk,
    const float* __restrict__ bias)
{
    const int j   = threadIdx.x & 31;
    const int wid = (blockIdx.x << 2) + (threadIdx.x >> 5);
    const int nw  = gridDim.x << 2;

    float wk0[EMBD], wk1[EMBD], wk2[EMBD], wk3[EMBD];
    #pragma unroll
    for (int e = 0; e < EMBD; e++){
        wk0[e] = Wk[e*GATE + j];
        wk1[e] = Wk[e*GATE + j + 32];
        wk2[e] = Wk[e*GATE + j + 64];
        wk3[e] = Wk[e*GATE + j + 96];
    }
    const float b0 = bias[j], b1 = bias[j+32], b2 = bias[j+64], b3 = bias[j+96];

    for (int v = wid; v < VOCAB; v += nw){
        const float* x = emb + v * EMBD;
        float zi = b0, zf = b1, zg = b2, zo = b3;
        #pragma unroll
        for (int e = 0; e < EMBD; e++){
            const float xe = x[e];
            zi = fmaf(xe, wk0[e], zi);
            zf = fmaf(xe, wk1[e], zf);
            zg = fmaf(xe, wk2[e], zg);
            zo = fmaf(xe, wk3[e], zo);
        }
        g_vp[(size_t)v * HIDD + j] = make_float4(zi, zf, zg, zo);
    }
}

// ─────────────── Phase 2: HFMA2 matvec with 4-deep chains ───────────────────
// R16 structure (one warp/seq, fp16x2 Wr matvec, duplicated {h,h} half2 h
// table, fp32 gates/c/h, vp gather, spill-proof named rings, barrier-free
// volatile STS->LDS handoff) with the accumulation restructured from 4x16-deep
// chains (64cy) to 16x4-deep chains (16cy) + 3-level HADD2 tree (12cy): one
// IF + one GO chain per LDS.128 result, so each chain starts as soon as its
// load lands. Step was latency-bound (R16: issue halved, time unchanged) —
// this attacks the dependency chain directly.
#define MAC4(aif, ago, R, base)                                   \
    aif = __hfma2(u32h2((R).x), wIF[(base)  ], aif);              \
    ago = __hfma2(u32h2((R).x), wGO[(base)  ], ago);              \
    aif = __hfma2(u32h2((R).y), wIF[(base)+1], aif);              \
    ago = __hfma2(u32h2((R).y), wGO[(base)+1], ago);              \
    aif = __hfma2(u32h2((R).z), wIF[(base)+2], aif);              \
    ago = __hfma2(u32h2((R).z), wGO[(base)+2], ago);              \
    aif = __hfma2(u32h2((R).w), wIF[(base)+3], aif);              \
    ago = __hfma2(u32h2((R).w), wGO[(base)+3], ago);

#define LSTM_BODY(Z, TKC, TKZ, tt)                                      \
{                                                                       \
    const float4 z4  = Z;                                               \
    const int    tok = TKC;                                             \
    TKC = tptr[min((tt) + 4, SEQ - 1)];   /* token for step tt+4 */     \
    Z   = vpj[(size_t)(TKZ) * HIDD];      /* zx for step tt+2  */       \
    const uint4 r0 = lds128u(hbase +   0u);                             \
    const uint4 r1 = lds128u(hbase +  16u);                             \
    const uint4 r2 = lds128u(hbase +  32u);                             \
    const uint4 r3 = lds128u(hbase +  48u);                             \
    const uint4 r4 = lds128u(hbase +  64u);                             \
    const uint4 r5 = lds128u(hbase +  80u);                             \
    const uint4 r6 = lds128u(hbase +  96u);                             \
    const uint4 r7 = lds128u(hbase + 112u);                             \
    __half2 aI0 = zeroh, aI1 = zeroh, aI2 = zeroh, aI3 = zeroh;         \
    __half2 aI4 = zeroh, aI5 = zeroh, aI6 = zeroh, aI7 = zeroh;         \
    __half2 aG0 = zeroh, aG1 = zeroh, aG2 = zeroh, aG3 = zeroh;         \
    __half2 aG4 = zeroh, aG5 = zeroh, aG6 = zeroh, aG7 = zeroh;         \
    MAC4(aI0, aG0, r0,  0)                                              \
    MAC4(aI1, aG1, r1,  4)                                              \
    MAC4(aI2, aG2, r2,  8)                                              \
    MAC4(aI3, aG3, r3, 12)                                              \
    MAC4(aI4, aG4, r4, 16)                                              \
    MAC4(aI5, aG5, r5, 20)                                              \
    MAC4(aI6, aG6, r6, 24)                                              \
    MAC4(aI7, aG7, r7, 28)                                              \
    const __half2 sIF = __hadd2(__hadd2(__hadd2(aI0, aI1), __hadd2(aI2, aI3)), \
                                __hadd2(__hadd2(aI4, aI5), __hadd2(aI6, aI7))); \
    const __half2 sGO = __hadd2(__hadd2(__hadd2(aG0, aG1), __hadd2(aG2, aG3)), \
                                __hadd2(__hadd2(aG4, aG5), __hadd2(aG6, aG7))); \
    const float2 fIF = __half22float2(sIF);                             \
    const float2 fGO = __half22float2(sGO);                             \
    const float gi = sigt(z4.x + fIF.x);                                \
    const float gf = sigt(z4.y + fIF.y);                                \
    const float gg = tanha(z4.z + fGO.x);                               \
    const float go = sigt(z4.w + fGO.y);                                \
    const float cn = fmaf(gf, c, gi * gg);                              \
    const float tc = tanha(cn);                                         \
    const bool  m  = (tok != 0);                                        \
    c = m ? cn : c;                                                     \
    h = m ? (go * tc) : h;                                              \
    sts32u(haddr, h2u32(__float2half2_rn(h)));                          \
    optr[(size_t)(tt) * HIDD] = h;                                      \
}

__global__ __launch_bounds__(128) void rec_kernel(
    const int*   __restrict__ tokens,
    const float* __restrict__ Wr,
    float*       __restrict__ out)
{
    __shared__ u32 hs[4][HIDD];           // {h,h} half2 per hid, per warp

    const int w = threadIdx.x >> 5;
    const int j = threadIdx.x & 31;
    const int b = blockIdx.x * 4 + w;

    // fp16x2 packed weights: wIF[k] = {wi[k], wf[k]}, wGO[k] = {wg[k], wo[k]}
    __half2 wIF[HIDD], wGO[HIDD];         // constant indices only
    #pragma unroll
    for (int k = 0; k < HIDD; k++){
        wIF[k] = __floats2half2_rn(Wr[k*GATE + j],      Wr[k*GATE + j + 32]);
        wGO[k] = __floats2half2_rn(Wr[k*GATE + j + 64], Wr[k*GATE + j + 96]);
    }
    const __half2 zeroh = __float2half2_rn(0.0f);

    const u32 hbase = smem_u32(hs[w]);
    const u32 haddr = hbase + (u32)j * 4u;

    const float4* __restrict__ vpj  = g_vp + j;
    const int*    __restrict__ tptr = tokens + b * SEQ;
    float* optr = out + (size_t)b * SEQ * HIDD + j;

    // token ring distance 4; z ring distance 2 (slot = t parity)
    int tA = tptr[0], tB = tptr[1], tC = tptr[2], tD = tptr[3];
    float4 zA = vpj[(size_t)tA * HIDD];
    float4 zB = vpj[(size_t)tB * HIDD];

    sts32u(haddr, 0u);
    float h = 0.0f, c = 0.0f;

    for (int t = 0; t < SEQ; t += 4){
        LSTM_BODY(zA, tA, tC, t + 0)
        LSTM_BODY(zB, tB, tD, t + 1)
        LSTM_BODY(zA, tC, tA, t + 2)
        LSTM_BODY(zB, tD, tB, t + 3)
    }
}

extern "C" void kernel_launch(void* const* d_in, const int* in_sizes, int n_in,
                              void* d_out, int out_size)
{
    (void)in_sizes; (void)n_in; (void)out_size;
    const int*   tokens = (const int*)  d_in[0];
    const float* emb    = (const float*)d_in[1];
    const float* Wk     = (const float*)d_in[2];
    const float* Wr     = (const float*)d_in[3];
    const float* bias   = (const float*)d_in[4];
    float* out = (float*)d_out;

    vproj_kernel<<<40, 128>>>(emb, Wk, bias);
    rec_kernel<<<BATCH / 4, 128>>>(tokens, Wr, out);
}